// round 10
// baseline (speedup 1.0000x reference)
#include <cuda_runtime.h>
#include <cuda_fp16.h>
#include <math.h>
#include <stdint.h>

#define NN   50000
#define NF   256
#define NHID 128
#define KHOP 4
#define NC   512      // KHOP * NHID
#define NE   800000
#define NO   64
#define SA   40       // gemm1 smem row stride (fp16 elems)
#define SB   136      // fused-kernel smem row stride (128 + 8 pad; word stride
                      // 68 = 4 mod 32 -> conflict-free mma frag loads)

#define NBIN (KHOP * NN)
#define NET  (KHOP * NE)
#define SCAN_BLK   256
#define SCAN_PER   16
#define SCAN_CHUNK (SCAN_BLK * SCAN_PER)
#define SCAN_NB    49

#define FUSED_SMEM (3 * 64 * SB * 2)   // Ash + Asl + Bs = 52224 B

// ---------------------------------------------------------------------------
// Scratch (__device__ globals per harness allocation rules)
// ---------------------------------------------------------------------------
__device__ __half g_h[(size_t)NN * NC];    // post-linear features, fp16
__device__ __half g_wt[KHOP * NHID * NF];  // W transposed [hop][n][k], fp16
__device__ __half g_wot[NO * NC];          // W_out transposed [n][k], fp16
__device__ int  g_cnt[NBIN];
__device__ int  g_rowptr[NBIN + 1];
__device__ int  g_cur[NBIN];
__device__ int  g_bsum[SCAN_NB];
__device__ int2 g_edge[NET];               // interleaved (col, val-bits)

// ---------------------------------------------------------------------------
// helpers
// ---------------------------------------------------------------------------
__device__ __forceinline__ void mma16816(float* d, const uint32_t* a, const uint32_t* b) {
    asm volatile(
        "mma.sync.aligned.m16n8k16.row.col.f32.f16.f16.f32 "
        "{%0,%1,%2,%3}, {%4,%5,%6,%7}, {%8,%9}, {%0,%1,%2,%3};\n"
        : "+f"(d[0]), "+f"(d[1]), "+f"(d[2]), "+f"(d[3])
        : "r"(a[0]), "r"(a[1]), "r"(a[2]), "r"(a[3]), "r"(b[0]), "r"(b[1]));
}

__device__ __forceinline__ uint32_t lds32(const __half* p) {
    return *reinterpret_cast<const uint32_t*>(p);
}

__device__ __forceinline__ void split_h(float v, __half& h, __half& l) {
    h = __float2half_rn(v);
    l = __float2half_rn(v - __half2float(h));
}

__device__ __forceinline__ void split8(float4 a, float4 b, uint4& hh, uint4& ll) {
    union { uint4 u; __half s[8]; } H, L;
    float v[8] = {a.x, a.y, a.z, a.w, b.x, b.y, b.z, b.w};
#pragma unroll
    for (int j = 0; j < 8; j++) split_h(v[j], H.s[j], L.s[j]);
    hh = H.u; ll = L.u;
}

__device__ __forceinline__ float elu1(float v) {
    return v > 0.f ? v : (__expf(v) - 1.f);
}

// ---------------------------------------------------------------------------
// Prep: zero CSR counters + both weight fp16 transposes.
// ---------------------------------------------------------------------------
__global__ __launch_bounds__(256) void prep(const float* __restrict__ W,
                                            const float* __restrict__ Wout) {
    const int idx = blockIdx.x * 256 + threadIdx.x;
    if (idx < NBIN) g_cnt[idx] = 0;
    if (idx < KHOP * NF * NHID) {
        int hop = idx / (NF * NHID);
        int rem = idx - hop * (NF * NHID);
        int k = rem / NHID;
        int n = rem - k * NHID;
        g_wt[(size_t)hop * NHID * NF + (size_t)n * NF + k] = __float2half_rn(W[idx]);
    }
    if (idx < NC * NO) {
        int k = idx / NO;
        int n = idx - k * NO;
        g_wot[(size_t)n * NC + k] = __float2half_rn(Wout[idx]);
    }
}

// ---------------------------------------------------------------------------
// CSR build: histogram -> two-level scan -> scatter (global across hops).
// ---------------------------------------------------------------------------
__global__ __launch_bounds__(256) void hist(const int* __restrict__ erows) {
    int e = blockIdx.x * 256 + threadIdx.x;
    if (e >= NET) return;
    int hop = e / NE;
    atomicAdd(&g_cnt[hop * NN + erows[e]], 1);
}

__global__ __launch_bounds__(SCAN_BLK) void scan1() {
    __shared__ int sh[SCAN_BLK];
    const int t = threadIdx.x;
    const int base = blockIdx.x * SCAN_CHUNK + t * SCAN_PER;
    int v[SCAN_PER];
    int tot = 0;
#pragma unroll
    for (int i = 0; i < SCAN_PER; i++) {
        v[i] = (base + i < NBIN) ? g_cnt[base + i] : 0;
        tot += v[i];
    }
    sh[t] = tot;
    __syncthreads();
    for (int off = 1; off < SCAN_BLK; off <<= 1) {
        int x = (t >= off) ? sh[t - off] : 0;
        __syncthreads();
        sh[t] += x;
        __syncthreads();
    }
    int run = sh[t] - tot;
#pragma unroll
    for (int i = 0; i < SCAN_PER; i++) {
        if (base + i < NBIN) g_rowptr[base + i] = run;
        run += v[i];
    }
    if (t == 0) g_bsum[blockIdx.x] = sh[SCAN_BLK - 1];
}

__global__ __launch_bounds__(256) void scan3() {
    int i = blockIdx.x * 256 + threadIdx.x;
    if (i < NBIN) {
        const int nb = i / SCAN_CHUNK;
        int pre = 0;
        for (int b = 0; b < nb; b++) pre += g_bsum[b];
        int v = g_rowptr[i] + pre;
        g_rowptr[i] = v;
        g_cur[i] = v;
    }
    if (i == 0) g_rowptr[NBIN] = NET;
}

__global__ __launch_bounds__(256) void scatter(const int* __restrict__ erows,
                                               const int* __restrict__ ecols,
                                               const float* __restrict__ evals) {
    int e = blockIdx.x * 256 + threadIdx.x;
    if (e >= NET) return;
    int hop = e / NE;
    int pos = atomicAdd(&g_cur[hop * NN + erows[e]], 1);
    g_edge[pos] = make_int2(ecols[e], __float_as_int(evals[e]));
}

// ---------------------------------------------------------------------------
// GEMM1 (tensor): g_h[n, hop*128+j] = fp16(x @ W[hop] + b[hop])
// 2-pass fp16-split. CTA 128x128, BK=32, 8 warps (4m x 2n), warp 32x64.
// ---------------------------------------------------------------------------
__global__ __launch_bounds__(256) void gemm1_mma(const float* __restrict__ x,
                                                 const float* __restrict__ bias) {
    const int hop = blockIdx.x;
    const int m0  = blockIdx.y * 128;

    __shared__ __half Ash[128 * SA], Asl[128 * SA];
    __shared__ __half Bs[128 * SA];

    const int t    = threadIdx.x;
    const int wid  = t >> 5, lane = t & 31;
    const int wm   = wid >> 1, wn = wid & 1;
    const int g    = lane >> 2, t4 = lane & 3;

    const int lr = t >> 2;
    const int lk = (t & 3) * 8;

    const __half* wt = g_wt + (size_t)hop * NHID * NF;

    float acc[2][8][4];
#pragma unroll
    for (int i = 0; i < 2; i++)
#pragma unroll
        for (int j = 0; j < 8; j++)
#pragma unroll
            for (int q = 0; q < 4; q++) acc[i][j][q] = 0.f;

    const float4 zf = make_float4(0.f, 0.f, 0.f, 0.f);
    float4 fx0a, fx0b, fx1a, fx1b;
    uint4 pb0, pb1;

    const int r0 = m0 + lr, r1 = m0 + lr + 64;
    {
        fx0a = (r0 < NN) ? *(const float4*)(x + (size_t)r0 * NF + lk)     : zf;
        fx0b = (r0 < NN) ? *(const float4*)(x + (size_t)r0 * NF + lk + 4) : zf;
        fx1a = (r1 < NN) ? *(const float4*)(x + (size_t)r1 * NF + lk)     : zf;
        fx1b = (r1 < NN) ? *(const float4*)(x + (size_t)r1 * NF + lk + 4) : zf;
        pb0  = *(const uint4*)(wt + (size_t)lr * NF + lk);
        pb1  = *(const uint4*)(wt + (size_t)(lr + 64) * NF + lk);
    }

    for (int k0 = 0; k0 < NF; k0 += 32) {
        __syncthreads();
        {
            uint4 hh, ll;
            split8(fx0a, fx0b, hh, ll);
            *(uint4*)&Ash[lr * SA + lk] = hh;
            *(uint4*)&Asl[lr * SA + lk] = ll;
            split8(fx1a, fx1b, hh, ll);
            *(uint4*)&Ash[(lr + 64) * SA + lk] = hh;
            *(uint4*)&Asl[(lr + 64) * SA + lk] = ll;
        }
        *(uint4*)&Bs[lr * SA + lk]        = pb0;
        *(uint4*)&Bs[(lr + 64) * SA + lk] = pb1;
        __syncthreads();

        const int kn = k0 + 32;
        if (kn < NF) {
            fx0a = (r0 < NN) ? *(const float4*)(x + (size_t)r0 * NF + kn + lk)     : zf;
            fx0b = (r0 < NN) ? *(const float4*)(x + (size_t)r0 * NF + kn + lk + 4) : zf;
            fx1a = (r1 < NN) ? *(const float4*)(x + (size_t)r1 * NF + kn + lk)     : zf;
            fx1b = (r1 < NN) ? *(const float4*)(x + (size_t)r1 * NF + kn + lk + 4) : zf;
            pb0  = *(const uint4*)(wt + (size_t)lr * NF + kn + lk);
            pb1  = *(const uint4*)(wt + (size_t)(lr + 64) * NF + kn + lk);
        }

#pragma unroll
        for (int ks = 0; ks < 2; ks++) {
            const int kb = ks * 16 + 2 * t4;
            uint32_t ah[2][4], al[2][4];
#pragma unroll
            for (int mf = 0; mf < 2; mf++) {
                const int rb = (wm * 32 + mf * 16 + g) * SA + kb;
                ah[mf][0] = lds32(&Ash[rb]);
                ah[mf][1] = lds32(&Ash[rb + 8 * SA]);
                ah[mf][2] = lds32(&Ash[rb + 8]);
                ah[mf][3] = lds32(&Ash[rb + 8 * SA + 8]);
                al[mf][0] = lds32(&Asl[rb]);
                al[mf][1] = lds32(&Asl[rb + 8 * SA]);
                al[mf][2] = lds32(&Asl[rb + 8]);
                al[mf][3] = lds32(&Asl[rb + 8 * SA + 8]);
            }
#pragma unroll
            for (int nf = 0; nf < 8; nf++) {
                const int nb = (wn * 64 + nf * 8 + g) * SA + kb;
                uint32_t bb[2];
                bb[0] = lds32(&Bs[nb]); bb[1] = lds32(&Bs[nb + 8]);
#pragma unroll
                for (int mf = 0; mf < 2; mf++) {
                    mma16816(acc[mf][nf], ah[mf], bb);
                    mma16816(acc[mf][nf], al[mf], bb);
                }
            }
        }
    }

    const int colbase = wn * 64 + 2 * t4;
#pragma unroll
    for (int mf = 0; mf < 2; mf++) {
        const int row = m0 + wm * 32 + mf * 16 + g;
#pragma unroll
        for (int nf = 0; nf < 8; nf++) {
            const int col = colbase + nf * 8;
            const float2 bv = *(const float2*)(bias + hop * NHID + col);
            if (row < NN) {
                *(__half2*)(g_h + (size_t)row * NC + hop * NHID + col) =
                    __floats2half2_rn(acc[mf][nf][0] + bv.x, acc[mf][nf][1] + bv.y);
            }
            if (row + 8 < NN) {
                *(__half2*)(g_h + (size_t)(row + 8) * NC + hop * NHID + col) =
                    __floats2half2_rn(acc[mf][nf][2] + bv.x, acc[mf][nf][3] + bv.y);
            }
        }
    }
}

// ---------------------------------------------------------------------------
// FUSED spmm + elu + output GEMM:
//   y[r] = b_out + sum_hop elu(spmm_hop(r)) @ W_out[hop*128:(hop+1)*128, :]
// 64-row tile, 256 threads. Per hop: 8 warps gather 8 rows each (fp32 reg
// accumulation on fp16 h, exactly the old spmm), elu + fp16-split into smem
// A-tiles; then 8 mma k-steps against the hop's 64x128 W_out slice. C lives
// in registers across hops; g_agg never exists. 52KB dynamic smem, ~3 CTA/SM.
// ---------------------------------------------------------------------------
extern __shared__ __half sm_f[];

__global__ __launch_bounds__(256) void spmm_gemm2(const float* __restrict__ bout,
                                                  float* __restrict__ y) {
    __half* Ash = sm_f;
    __half* Asl = Ash + 64 * SB;
    __half* Bs  = Asl + 64 * SB;

    const int m0  = blockIdx.x * 64;
    const int t   = threadIdx.x;
    const int wid = t >> 5, lane = t & 31;
    const int wm  = wid >> 1, wn = wid & 1;
    const int g   = lane >> 2, t4 = lane & 3;

    float acc[4][4];
#pragma unroll
    for (int j = 0; j < 4; j++)
#pragma unroll
        for (int q = 0; q < 4; q++) acc[j][q] = 0.f;

    for (int hop = 0; hop < KHOP; hop++) {
        __syncthreads();   // previous hop's mma done with smem

        // --- load W_out slice [64 n-rows x 128 k] into Bs ---
        {
            const int row = t >> 2;
            const int c0  = (t & 3) * 32;
            const __half* src = g_wot + (size_t)row * NC + hop * NHID + c0;
#pragma unroll
            for (int q = 0; q < 4; q++)
                *(uint4*)&Bs[row * SB + c0 + q * 8] = *(const uint4*)(src + q * 8);
        }

        // --- gather: each warp accumulates 8 rows, elu+split into Ash/Asl ---
        const __half* hb = g_h + hop * NHID + lane * 4;
#pragma unroll 1
        for (int i = 0; i < 8; i++) {
            const int lr   = wid + 8 * i;    // strided: averages edge-count variance
            const int grow = m0 + lr;
            float4 a4 = make_float4(0.f, 0.f, 0.f, 0.f);
            if (grow < NN) {
                const int bin = hop * NN + grow;
                const int s = g_rowptr[bin];
                const int e = g_rowptr[bin + 1];
                for (int p = s; p < e; p += 32) {
                    const int n = min(32, e - p);
                    int2 ed = (lane < n) ? g_edge[p + lane] : make_int2(0, 0);
                    const int   c = ed.x;
                    const float v = __int_as_float(ed.y);
                    int j = 0;
                    for (; j + 4 <= n; j += 4) {
                        int   c0 = __shfl_sync(0xffffffffu, c, j);
                        int   c1 = __shfl_sync(0xffffffffu, c, j + 1);
                        int   c2 = __shfl_sync(0xffffffffu, c, j + 2);
                        int   c3 = __shfl_sync(0xffffffffu, c, j + 3);
                        float v0 = __shfl_sync(0xffffffffu, v, j);
                        float v1 = __shfl_sync(0xffffffffu, v, j + 1);
                        float v2 = __shfl_sync(0xffffffffu, v, j + 2);
                        float v3 = __shfl_sync(0xffffffffu, v, j + 3);
                        uint2 u0 = *(const uint2*)(hb + (size_t)c0 * NC);
                        uint2 u1 = *(const uint2*)(hb + (size_t)c1 * NC);
                        uint2 u2 = *(const uint2*)(hb + (size_t)c2 * NC);
                        uint2 u3 = *(const uint2*)(hb + (size_t)c3 * NC);
                        float2 a0 = __half22float2(*(__half2*)&u0.x);
                        float2 b0 = __half22float2(*(__half2*)&u0.y);
                        float2 a1 = __half22float2(*(__half2*)&u1.x);
                        float2 b1 = __half22float2(*(__half2*)&u1.y);
                        float2 a2 = __half22float2(*(__half2*)&u2.x);
                        float2 b2 = __half22float2(*(__half2*)&u2.y);
                        float2 a3 = __half22float2(*(__half2*)&u3.x);
                        float2 b3 = __half22float2(*(__half2*)&u3.y);
                        a4.x = fmaf(v0, a0.x, a4.x); a4.y = fmaf(v0, a0.y, a4.y);
                        a4.z = fmaf(v0, b0.x, a4.z); a4.w = fmaf(v0, b0.y, a4.w);
                        a4.x = fmaf(v1, a1.x, a4.x); a4.y = fmaf(v1, a1.y, a4.y);
                        a4.z = fmaf(v1, b1.x, a4.z); a4.w = fmaf(v1, b1.y, a4.w);
                        a4.x = fmaf(v2, a2.x, a4.x); a4.y = fmaf(v2, a2.y, a4.y);
                        a4.z = fmaf(v2, b2.x, a4.z); a4.w = fmaf(v2, b2.y, a4.w);
                        a4.x = fmaf(v3, a3.x, a4.x); a4.y = fmaf(v3, a3.y, a4.y);
                        a4.z = fmaf(v3, b3.x, a4.z); a4.w = fmaf(v3, b3.y, a4.w);
                    }
                    for (; j < n; j++) {
                        int   cj = __shfl_sync(0xffffffffu, c, j);
                        float vj = __shfl_sync(0xffffffffu, v, j);
                        uint2 u = *(const uint2*)(hb + (size_t)cj * NC);
                        float2 a = __half22float2(*(__half2*)&u.x);
                        float2 b = __half22float2(*(__half2*)&u.y);
                        a4.x = fmaf(vj, a.x, a4.x); a4.y = fmaf(vj, a.y, a4.y);
                        a4.z = fmaf(vj, b.x, a4.z); a4.w = fmaf(vj, b.y, a4.w);
                    }
                }
            }
            // elu + hi/lo split, store lane's 4 features (8B hi + 8B lo)
            a4.x = elu1(a4.x); a4.y = elu1(a4.y);
            a4.z = elu1(a4.z); a4.w = elu1(a4.w);
            union { uint2 u; __half s[4]; } H, L;
            split_h(a4.x, H.s[0], L.s[0]);
            split_h(a4.y, H.s[1], L.s[1]);
            split_h(a4.z, H.s[2], L.s[2]);
            split_h(a4.w, H.s[3], L.s[3]);
            *(uint2*)&Ash[lr * SB + lane * 4] = H.u;
            *(uint2*)&Asl[lr * SB + lane * 4] = L.u;
        }
        __syncthreads();

        // --- mma: K=128 of this hop, 2-pass fp16-split ---
#pragma unroll
        for (int ks = 0; ks < 8; ks++) {
            const int kb = ks * 16 + 2 * t4;
            uint32_t ah[4], al[4];
            const int rb = (wm * 16 + g) * SB + kb;
            ah[0] = lds32(&Ash[rb]);
            ah[1] = lds32(&Ash[rb + 8 * SB]);
            ah[2] = lds32(&Ash[rb + 8]);
            ah[3] = lds32(&Ash[rb + 8 * SB + 8]);
            al[0] = lds32(&Asl[rb]);
            al[1] = lds32(&Asl[rb + 8 * SB]);
            al[2] = lds32(&Asl[rb + 8]);
            al[3] = lds32(&Asl[rb + 8 * SB + 8]);
#pragma unroll
            for (int nf = 0; nf < 4; nf++) {
                const int nb = (wn * 32 + nf * 8 + g) * SB + kb;
                uint32_t bb[2];
                bb[0] = lds32(&Bs[nb]); bb[1] = lds32(&Bs[nb + 8]);
                mma16816(acc[nf], ah, bb);
                mma16816(acc[nf], al, bb);
            }
        }
    }

    // epilogue: + b_out, write y
    const int colbase = wn * 32 + 2 * t4;
    const int row = m0 + wm * 16 + g;
#pragma unroll
    for (int nf = 0; nf < 4; nf++) {
        const int col = colbase + nf * 8;
        const float2 bv = *(const float2*)(bout + col);
        if (row < NN) {
            float2 o;
            o.x = acc[nf][0] + bv.x;
            o.y = acc[nf][1] + bv.y;
            *(float2*)(y + (size_t)row * NO + col) = o;
        }
        if (row + 8 < NN) {
            float2 o;
            o.x = acc[nf][2] + bv.x;
            o.y = acc[nf][3] + bv.y;
            *(float2*)(y + (size_t)(row + 8) * NO + col) = o;
        }
    }
}

// ---------------------------------------------------------------------------
// Launch. Inputs: x, W, b, W_out, b_out, edge_rows, edge_cols, edge_vals.
// ---------------------------------------------------------------------------
extern "C" void kernel_launch(void* const* d_in, const int* in_sizes, int n_in,
                              void* d_out, int out_size) {
    (void)in_sizes; (void)n_in; (void)out_size;
    const float* x     = (const float*)d_in[0];
    const float* W     = (const float*)d_in[1];
    const float* b     = (const float*)d_in[2];
    const float* Wout  = (const float*)d_in[3];
    const float* bout  = (const float*)d_in[4];
    const int*   erows = (const int*)d_in[5];
    const int*   ecols = (const int*)d_in[6];
    const float* evals = (const float*)d_in[7];
    float* y = (float*)d_out;

    // allow >48KB dynamic smem (idempotent host-state call; not a stream op)
    cudaFuncSetAttribute(spmm_gemm2,
                         cudaFuncAttributeMaxDynamicSharedMemorySize, FUSED_SMEM);

    // prep + CSR build
    prep<<<(NBIN + 255) / 256, 256>>>(W, Wout);
    hist<<<NET / 256, 256>>>(erows);
    scan1<<<SCAN_NB, SCAN_BLK>>>();
    scan3<<<(NBIN + 255) / 256, 256>>>();
    scatter<<<NET / 256, 256>>>(erows, ecols, evals);

    // per-hop linear on tensor cores, fp16 h output
    gemm1_mma<<<dim3(KHOP, (NN + 127) / 128), 256>>>(x, b);

    // fused spmm + elu + output projection (no g_agg round trip)
    spmm_gemm2<<<(NN + 63) / 64, 256, FUSED_SMEM>>>(bout, y);
}

// round 12
// speedup vs baseline: 1.5730x; 1.5730x over previous
#include <cuda_runtime.h>
#include <cuda_fp16.h>
#include <math.h>
#include <stdint.h>

#define NN   50000
#define NF   256
#define NHID 128
#define KHOP 4
#define NC   512      // KHOP * NHID
#define NE   800000
#define NO   64
#define SA   40       // smem row stride in fp16 elems (80B, conflict-free frags)

#define NBIN (KHOP * NN)        // 200000 row bins across all hops
#define NET  (KHOP * NE)        // 3200000 edges total
#define SCAN_BLK   256
#define SCAN_PER   16
#define SCAN_CHUNK (SCAN_BLK * SCAN_PER)   // 4096
#define SCAN_NB    49                       // ceil(NBIN / SCAN_CHUNK)

// ---------------------------------------------------------------------------
// Scratch (__device__ globals per harness allocation rules)
// ---------------------------------------------------------------------------
__device__ __half g_h[(size_t)NN * NC];    // post-linear features, fp16
__device__ float  g_agg[(size_t)NN * NC];  // SpMM output, fp32 (written once)
__device__ __half g_wt[KHOP * NHID * NF];  // W transposed [hop][n][k], fp16
__device__ __half g_wot[NO * NC];          // W_out transposed [n][k], fp16
// CSR build (recomputed every call; deterministic work)
__device__ int  g_cnt[NBIN];
__device__ int  g_rowptr[NBIN + 1];
__device__ int  g_cur[NBIN];
__device__ int  g_bsum[SCAN_NB];
__device__ int2 g_edge[NET];               // interleaved (col, val-bits)

// ---------------------------------------------------------------------------
// mma.sync m16n8k16 fp16 -> f32, helpers
// ---------------------------------------------------------------------------
__device__ __forceinline__ void mma16816(float* d, const uint32_t* a, const uint32_t* b) {
    asm volatile(
        "mma.sync.aligned.m16n8k16.row.col.f32.f16.f16.f32 "
        "{%0,%1,%2,%3}, {%4,%5,%6,%7}, {%8,%9}, {%0,%1,%2,%3};\n"
        : "+f"(d[0]), "+f"(d[1]), "+f"(d[2]), "+f"(d[3])
        : "r"(a[0]), "r"(a[1]), "r"(a[2]), "r"(a[3]), "r"(b[0]), "r"(b[1]));
}

__device__ __forceinline__ uint32_t lds32(const __half* p) {
    return *reinterpret_cast<const uint32_t*>(p);
}

// convert 8 floats (2x float4) to 8 packed fp16
__device__ __forceinline__ uint4 cvt8(float4 a, float4 b) {
    union { uint4 u; __half2 s[4]; } U;
    U.s[0] = __floats2half2_rn(a.x, a.y);
    U.s[1] = __floats2half2_rn(a.z, a.w);
    U.s[2] = __floats2half2_rn(b.x, b.y);
    U.s[3] = __floats2half2_rn(b.z, b.w);
    return U.u;
}

__device__ __forceinline__ float elu1(float v) {
    return v > 0.f ? v : (__expf(v) - 1.f);
}

// ---------------------------------------------------------------------------
// Prep: zero CSR counters + both weight fp16 transposes, one kernel.
// ---------------------------------------------------------------------------
__global__ __launch_bounds__(256) void prep(const float* __restrict__ W,
                                            const float* __restrict__ Wout) {
    const int idx = blockIdx.x * 256 + threadIdx.x;
    if (idx < NBIN) g_cnt[idx] = 0;
    if (idx < KHOP * NF * NHID) {
        int hop = idx / (NF * NHID);
        int rem = idx - hop * (NF * NHID);
        int k = rem / NHID;
        int n = rem - k * NHID;
        g_wt[(size_t)hop * NHID * NF + (size_t)n * NF + k] = __float2half_rn(W[idx]);
    }
    if (idx < NC * NO) {
        int k = idx / NO;
        int n = idx - k * NO;
        g_wot[(size_t)n * NC + k] = __float2half_rn(Wout[idx]);
    }
}

// ---------------------------------------------------------------------------
// CSR build: histogram -> two-level scan -> scatter (global across hops).
// ---------------------------------------------------------------------------
__global__ __launch_bounds__(256) void hist(const int* __restrict__ erows) {
    int e = blockIdx.x * 256 + threadIdx.x;
    if (e >= NET) return;
    int hop = e / NE;
    atomicAdd(&g_cnt[hop * NN + erows[e]], 1);
}

__global__ __launch_bounds__(SCAN_BLK) void scan1() {
    __shared__ int sh[SCAN_BLK];
    const int t = threadIdx.x;
    const int base = blockIdx.x * SCAN_CHUNK + t * SCAN_PER;
    int v[SCAN_PER];
    int tot = 0;
#pragma unroll
    for (int i = 0; i < SCAN_PER; i++) {
        v[i] = (base + i < NBIN) ? g_cnt[base + i] : 0;
        tot += v[i];
    }
    sh[t] = tot;
    __syncthreads();
    for (int off = 1; off < SCAN_BLK; off <<= 1) {
        int x = (t >= off) ? sh[t - off] : 0;
        __syncthreads();
        sh[t] += x;
        __syncthreads();
    }
    int run = sh[t] - tot;
#pragma unroll
    for (int i = 0; i < SCAN_PER; i++) {
        if (base + i < NBIN) g_rowptr[base + i] = run;
        run += v[i];
    }
    if (t == 0) g_bsum[blockIdx.x] = sh[SCAN_BLK - 1];
}

__global__ __launch_bounds__(256) void scan3() {
    int i = blockIdx.x * 256 + threadIdx.x;
    if (i < NBIN) {
        const int nb = i / SCAN_CHUNK;
        int pre = 0;
        for (int b = 0; b < nb; b++) pre += g_bsum[b];
        int v = g_rowptr[i] + pre;
        g_rowptr[i] = v;
        g_cur[i] = v;
    }
    if (i == 0) g_rowptr[NBIN] = NET;
}

__global__ __launch_bounds__(256) void scatter(const int* __restrict__ erows,
                                               const int* __restrict__ ecols,
                                               const float* __restrict__ evals) {
    int e = blockIdx.x * 256 + threadIdx.x;
    if (e >= NET) return;
    int hop = e / NE;
    int pos = atomicAdd(&g_cur[hop * NN + erows[e]], 1);
    g_edge[pos] = make_int2(ecols[e], __float_as_int(evals[e]));
}

// ---------------------------------------------------------------------------
// GEMM1 (tensor): g_h[n, hop*128+j] = fp16(x @ W[hop] + b[hop])
// Single-pass pure-fp16 mma (x rounded to fp16; error budget verified).
// CTA tile 128x128, BK=32, 8 warps (4m x 2n), warp tile 32x64.
// ---------------------------------------------------------------------------
__global__ __launch_bounds__(256) void gemm1_mma(const float* __restrict__ x,
                                                 const float* __restrict__ bias) {
    const int hop = blockIdx.x;
    const int m0  = blockIdx.y * 128;

    __shared__ __half As[128 * SA];
    __shared__ __half Bs[128 * SA];

    const int t    = threadIdx.x;
    const int wid  = t >> 5, lane = t & 31;
    const int wm   = wid >> 1, wn = wid & 1;
    const int g    = lane >> 2, t4 = lane & 3;

    const int lr = t >> 2;          // 0..63
    const int lk = (t & 3) * 8;     // 0,8,16,24

    const __half* wt = g_wt + (size_t)hop * NHID * NF;

    float acc[2][8][4];
#pragma unroll
    for (int i = 0; i < 2; i++)
#pragma unroll
        for (int j = 0; j < 8; j++)
#pragma unroll
            for (int q = 0; q < 4; q++) acc[i][j][q] = 0.f;

    const float4 zf = make_float4(0.f, 0.f, 0.f, 0.f);
    float4 fx0a, fx0b, fx1a, fx1b;
    uint4 pb0, pb1;

    const int r0 = m0 + lr, r1 = m0 + lr + 64;
    {   // prefetch k0 = 0
        fx0a = (r0 < NN) ? *(const float4*)(x + (size_t)r0 * NF + lk)     : zf;
        fx0b = (r0 < NN) ? *(const float4*)(x + (size_t)r0 * NF + lk + 4) : zf;
        fx1a = (r1 < NN) ? *(const float4*)(x + (size_t)r1 * NF + lk)     : zf;
        fx1b = (r1 < NN) ? *(const float4*)(x + (size_t)r1 * NF + lk + 4) : zf;
        pb0  = *(const uint4*)(wt + (size_t)lr * NF + lk);
        pb1  = *(const uint4*)(wt + (size_t)(lr + 64) * NF + lk);
    }

    for (int k0 = 0; k0 < NF; k0 += 32) {
        __syncthreads();
        *(uint4*)&As[lr * SA + lk]        = cvt8(fx0a, fx0b);
        *(uint4*)&As[(lr + 64) * SA + lk] = cvt8(fx1a, fx1b);
        *(uint4*)&Bs[lr * SA + lk]        = pb0;
        *(uint4*)&Bs[(lr + 64) * SA + lk] = pb1;
        __syncthreads();

        const int kn = k0 + 32;
        if (kn < NF) {   // prefetch next K-block
            fx0a = (r0 < NN) ? *(const float4*)(x + (size_t)r0 * NF + kn + lk)     : zf;
            fx0b = (r0 < NN) ? *(const float4*)(x + (size_t)r0 * NF + kn + lk + 4) : zf;
            fx1a = (r1 < NN) ? *(const float4*)(x + (size_t)r1 * NF + kn + lk)     : zf;
            fx1b = (r1 < NN) ? *(const float4*)(x + (size_t)r1 * NF + kn + lk + 4) : zf;
            pb0  = *(const uint4*)(wt + (size_t)lr * NF + kn + lk);
            pb1  = *(const uint4*)(wt + (size_t)(lr + 64) * NF + kn + lk);
        }

#pragma unroll
        for (int ks = 0; ks < 2; ks++) {
            const int kb = ks * 16 + 2 * t4;
            uint32_t a[2][4];
#pragma unroll
            for (int mf = 0; mf < 2; mf++) {
                const int rb = (wm * 32 + mf * 16 + g) * SA + kb;
                a[mf][0] = lds32(&As[rb]);
                a[mf][1] = lds32(&As[rb + 8 * SA]);
                a[mf][2] = lds32(&As[rb + 8]);
                a[mf][3] = lds32(&As[rb + 8 * SA + 8]);
            }
#pragma unroll
            for (int nf = 0; nf < 8; nf++) {
                const int nb = (wn * 64 + nf * 8 + g) * SA + kb;
                uint32_t bb[2];
                bb[0] = lds32(&Bs[nb]); bb[1] = lds32(&Bs[nb + 8]);
#pragma unroll
                for (int mf = 0; mf < 2; mf++)
                    mma16816(acc[mf][nf], a[mf], bb);
            }
        }
    }

    const int colbase = wn * 64 + 2 * t4;
#pragma unroll
    for (int mf = 0; mf < 2; mf++) {
        const int row = m0 + wm * 32 + mf * 16 + g;
#pragma unroll
        for (int nf = 0; nf < 8; nf++) {
            const int col = colbase + nf * 8;
            const float2 bv = *(const float2*)(bias + hop * NHID + col);
            if (row < NN) {
                *(__half2*)(g_h + (size_t)row * NC + hop * NHID + col) =
                    __floats2half2_rn(acc[mf][nf][0] + bv.x, acc[mf][nf][1] + bv.y);
            }
            if (row + 8 < NN) {
                *(__half2*)(g_h + (size_t)(row + 8) * NC + hop * NHID + col) =
                    __floats2half2_rn(acc[mf][nf][2] + bv.x, acc[mf][nf][3] + bv.y);
            }
        }
    }
}

// ---------------------------------------------------------------------------
// CSR SpMM, all hops in one launch (fp16 h: whole 51.2MB set is L2-resident).
// One warp per row, fp32 register accumulation, single fp32 write. Lane owns
// 4 features (8B fp16 gather per edge). Interleaved (col,val) edge records.
// ---------------------------------------------------------------------------
__global__ __launch_bounds__(256) void spmm_csr() {
    const int row  = (blockIdx.x * 256 + threadIdx.x) >> 5;
    const int lane = threadIdx.x & 31;
    if (row >= NN) return;
    const int hop = blockIdx.y;

    const int bin = hop * NN + row;
    const int s = g_rowptr[bin];
    const int e = g_rowptr[bin + 1];

    const __half* hb = g_h + hop * NHID + lane * 4;
    float4 acc = make_float4(0.f, 0.f, 0.f, 0.f);

    for (int p = s; p < e; p += 32) {
        const int n = min(32, e - p);
        int2 ed = (lane < n) ? g_edge[p + lane] : make_int2(0, 0);
        const int   c = ed.x;
        const float v = __int_as_float(ed.y);
        int j = 0;
        for (; j + 4 <= n; j += 4) {
            int   c0 = __shfl_sync(0xffffffffu, c, j);
            int   c1 = __shfl_sync(0xffffffffu, c, j + 1);
            int   c2 = __shfl_sync(0xffffffffu, c, j + 2);
            int   c3 = __shfl_sync(0xffffffffu, c, j + 3);
            float v0 = __shfl_sync(0xffffffffu, v, j);
            float v1 = __shfl_sync(0xffffffffu, v, j + 1);
            float v2 = __shfl_sync(0xffffffffu, v, j + 2);
            float v3 = __shfl_sync(0xffffffffu, v, j + 3);
            uint2 u0 = *(const uint2*)(hb + (size_t)c0 * NC);
            uint2 u1 = *(const uint2*)(hb + (size_t)c1 * NC);
            uint2 u2 = *(const uint2*)(hb + (size_t)c2 * NC);
            uint2 u3 = *(const uint2*)(hb + (size_t)c3 * NC);
            float2 a0 = __half22float2(*(__half2*)&u0.x);
            float2 b0 = __half22float2(*(__half2*)&u0.y);
            float2 a1 = __half22float2(*(__half2*)&u1.x);
            float2 b1 = __half22float2(*(__half2*)&u1.y);
            float2 a2 = __half22float2(*(__half2*)&u2.x);
            float2 b2 = __half22float2(*(__half2*)&u2.y);
            float2 a3 = __half22float2(*(__half2*)&u3.x);
            float2 b3 = __half22float2(*(__half2*)&u3.y);
            acc.x = fmaf(v0, a0.x, acc.x); acc.y = fmaf(v0, a0.y, acc.y);
            acc.z = fmaf(v0, b0.x, acc.z); acc.w = fmaf(v0, b0.y, acc.w);
            acc.x = fmaf(v1, a1.x, acc.x); acc.y = fmaf(v1, a1.y, acc.y);
            acc.z = fmaf(v1, b1.x, acc.z); acc.w = fmaf(v1, b1.y, acc.w);
            acc.x = fmaf(v2, a2.x, acc.x); acc.y = fmaf(v2, a2.y, acc.y);
            acc.z = fmaf(v2, b2.x, acc.z); acc.w = fmaf(v2, b2.y, acc.w);
            acc.x = fmaf(v3, a3.x, acc.x); acc.y = fmaf(v3, a3.y, acc.y);
            acc.z = fmaf(v3, b3.x, acc.z); acc.w = fmaf(v3, b3.y, acc.w);
        }
        for (; j < n; j++) {
            int   cj = __shfl_sync(0xffffffffu, c, j);
            float vj = __shfl_sync(0xffffffffu, v, j);
            uint2 u = *(const uint2*)(hb + (size_t)cj * NC);
            float2 a = __half22float2(*(__half2*)&u.x);
            float2 b = __half22float2(*(__half2*)&u.y);
            acc.x = fmaf(vj, a.x, acc.x); acc.y = fmaf(vj, a.y, acc.y);
            acc.z = fmaf(vj, b.x, acc.z); acc.w = fmaf(vj, b.y, acc.w);
        }
    }

    *(float4*)(g_agg + (size_t)row * NC + hop * NHID + lane * 4) = acc;
}

// ---------------------------------------------------------------------------
// GEMM2 (tensor): y = elu(agg) @ W_out + b_out.
// Single-pass pure-fp16 (elu fused into A stage). CTA tile 128x64, BK=32,
// 8 warps (4m x 2n), warp tile 32x32.
// ---------------------------------------------------------------------------
__global__ __launch_bounds__(256) void gemm2_mma(const float* __restrict__ bout,
                                                 float* __restrict__ y) {
    const int m0 = blockIdx.x * 128;

    __shared__ __half As[128 * SA];
    __shared__ __half Bs[64 * SA];

    const int t   = threadIdx.x;
    const int wid = t >> 5, lane = t & 31;
    const int wm  = wid >> 1, wn = wid & 1;
    const int g   = lane >> 2, t4 = lane & 3;

    const int ar = t >> 1;          // A row 0..127
    const int ac = (t & 1) * 16;    // A col block (16 f32)
    const int br = t >> 2;          // B row (n) 0..63
    const int bk = (t & 3) * 8;     // B col block (8 fp16)

    const int arow = m0 + ar;
    const bool aok = arow < NN;

    float acc[2][4][4];
#pragma unroll
    for (int i = 0; i < 2; i++)
#pragma unroll
        for (int j = 0; j < 4; j++)
#pragma unroll
            for (int q = 0; q < 4; q++) acc[i][j][q] = 0.f;

    const float4 zf = make_float4(0.f, 0.f, 0.f, 0.f);
    float4 fa[4];
    uint4 pb;

    {
        const float* ap = g_agg + (size_t)arow * NC + ac;
#pragma unroll
        for (int q = 0; q < 4; q++)
            fa[q] = aok ? *(const float4*)(ap + q * 4) : zf;
        pb = *(const uint4*)(g_wot + (size_t)br * NC + bk);
    }

    for (int k0 = 0; k0 < NC; k0 += 32) {
        __syncthreads();
#pragma unroll
        for (int q = 0; q < 2; q++) {
            float4 va = fa[2 * q], vb = fa[2 * q + 1];
            va.x = elu1(va.x); va.y = elu1(va.y); va.z = elu1(va.z); va.w = elu1(va.w);
            vb.x = elu1(vb.x); vb.y = elu1(vb.y); vb.z = elu1(vb.z); vb.w = elu1(vb.w);
            *(uint4*)&As[ar * SA + ac + q * 8] = cvt8(va, vb);
        }
        *(uint4*)&Bs[br * SA + bk] = pb;
        __syncthreads();

        const int kn = k0 + 32;
        if (kn < NC) {
            const float* ap = g_agg + (size_t)arow * NC + kn + ac;
#pragma unroll
            for (int q = 0; q < 4; q++)
                fa[q] = aok ? *(const float4*)(ap + q * 4) : zf;
            pb = *(const uint4*)(g_wot + (size_t)br * NC + kn + bk);
        }

#pragma unroll
        for (int ks = 0; ks < 2; ks++) {
            const int kb = ks * 16 + 2 * t4;
            uint32_t a[2][4];
#pragma unroll
            for (int mf = 0; mf < 2; mf++) {
                const int rb = (wm * 32 + mf * 16 + g) * SA + kb;
                a[mf][0] = lds32(&As[rb]);
                a[mf][1] = lds32(&As[rb + 8 * SA]);
                a[mf][2] = lds32(&As[rb + 8]);
                a[mf][3] = lds32(&As[rb + 8 * SA + 8]);
            }
#pragma unroll
            for (int nf = 0; nf < 4; nf++) {
                const int nb = (wn * 32 + nf * 8 + g) * SA + kb;
                uint32_t bb[2];
                bb[0] = lds32(&Bs[nb]); bb[1] = lds32(&Bs[nb + 8]);
#pragma unroll
                for (int mf = 0; mf < 2; mf++)
                    mma16816(acc[mf][nf], a[mf], bb);
            }
        }
    }

    const int colbase = wn * 32 + 2 * t4;
#pragma unroll
    for (int mf = 0; mf < 2; mf++) {
        const int row = m0 + wm * 32 + mf * 16 + g;
#pragma unroll
        for (int nf = 0; nf < 4; nf++) {
            const int col = colbase + nf * 8;
            const float2 bv = *(const float2*)(bout + col);
            if (row < NN) {
                float2 o;
                o.x = acc[mf][nf][0] + bv.x;
                o.y = acc[mf][nf][1] + bv.y;
                *(float2*)(y + (size_t)row * NO + col) = o;
            }
            if (row + 8 < NN) {
                float2 o;
                o.x = acc[mf][nf][2] + bv.x;
                o.y = acc[mf][nf][3] + bv.y;
                *(float2*)(y + (size_t)(row + 8) * NO + col) = o;
            }
        }
    }
}

// ---------------------------------------------------------------------------
// Launch. Inputs: x, W, b, W_out, b_out, edge_rows, edge_cols, edge_vals.
// ---------------------------------------------------------------------------
extern "C" void kernel_launch(void* const* d_in, const int* in_sizes, int n_in,
                              void* d_out, int out_size) {
    (void)in_sizes; (void)n_in; (void)out_size;
    const float* x     = (const float*)d_in[0];
    const float* W     = (const float*)d_in[1];
    const float* b     = (const float*)d_in[2];
    const float* Wout  = (const float*)d_in[3];
    const float* bout  = (const float*)d_in[4];
    const int*   erows = (const int*)d_in[5];
    const int*   ecols = (const int*)d_in[6];
    const float* evals = (const float*)d_in[7];
    float* y = (float*)d_out;

    // prep (zero counters + weight fp16 transposes) and CSR build
    prep<<<(NBIN + 255) / 256, 256>>>(W, Wout);
    hist<<<NET / 256, 256>>>(erows);
    scan1<<<SCAN_NB, SCAN_BLK>>>();
    scan3<<<(NBIN + 255) / 256, 256>>>();
    scatter<<<NET / 256, 256>>>(erows, ecols, evals);

    // per-hop linear on tensor cores (single-pass fp16), fp16 h output
    gemm1_mma<<<dim3(KHOP, (NN + 127) / 128), 256>>>(x, b);

    // CSR SpMM, all hops in one launch (fp16 h fits L2 in full)
    spmm_csr<<<dim3((NN * 32 + 255) / 256, KHOP), 256>>>();

    // elu + output projection on tensor cores (single-pass fp16)
    gemm2_mma<<<(NN + 127) / 128, 256>>>(bout, y);
}